// round 16
// baseline (speedup 1.0000x reference)
#include <cuda_runtime.h>
#include <cuda_fp16.h>
#include <cstdint>

// Problem constants
#define B_   128
#define N_   4608
#define IL_  8
#define C_   10
#define L_   16
#define KDIM 160          // C_*L_
#define SROW (B_*KDIM)    // 20480

typedef unsigned long long u64t;

// packed f32x2 helpers (sm_103a FFMA2 path — PTX only)
__device__ __forceinline__ u64t pk2(float lo, float hi) {
    u64t r; asm("mov.b64 %0,{%1,%2};" : "=l"(r) : "f"(lo), "f"(hi)); return r;
}
__device__ __forceinline__ void upk2(u64t v, float& lo, float& hi) {
    asm("mov.b64 {%0,%1},%2;" : "=f"(lo), "=f"(hi) : "l"(v));
}
__device__ __forceinline__ u64t ffma2(u64t a, u64t b, u64t c) {
    u64t d; asm("fma.rn.f32x2 %0,%1,%2,%3;" : "=l"(d) : "l"(a), "l"(b), "l"(c));
    return d;
}
__device__ __forceinline__ u64t fmul2(u64t a, u64t b) {
    u64t d; asm("mul.rn.f32x2 %0,%1,%2;" : "=l"(d) : "l"(a), "l"(b)); return d;
}
__device__ __forceinline__ u64t fadd2(u64t a, u64t b) {
    u64t d; asm("add.rn.f32x2 %0,%1,%2;" : "=l"(d) : "l"(a), "l"(b)); return d;
}

// Scratch (allocation-free rule: __device__ globals)
__device__ __half g_uh[(size_t)B_ * N_ * KDIM];   // 188 MB prediction tensor
__device__ float  g_s[3][SROW];                   // s accumulators per round
__device__ unsigned g_cnt_gemm[8];                // per 16-b group, target 128
__device__ unsigned g_cnt_r1[B_];                 // per b, target 2
__device__ unsigned g_cnt_r2[B_];                 // per b, target 2

// ---------------------------------------------------------------------------
// Zero s accumulators + counters (every replay)
// ---------------------------------------------------------------------------
__global__ void k_zero() {
    int i = blockIdx.x * blockDim.x + threadIdx.x;
    if (i < 3 * SROW) ((float*)g_s)[i] = 0.0f;
    if (i < 8)   g_cnt_gemm[i] = 0u;
    if (i < B_) { g_cnt_r1[i] = 0u; g_cnt_r2[i] = 0u; }
}

// ---------------------------------------------------------------------------
// squash on one element in an aligned 16-lane group
// ---------------------------------------------------------------------------
#define FULLM 0xffffffffu
__device__ __forceinline__ float squash16(float val) {
    float sq = val * val;
    sq += __shfl_xor_sync(FULLM, sq, 8);
    sq += __shfl_xor_sync(FULLM, sq, 4);
    sq += __shfl_xor_sync(FULLM, sq, 2);
    sq += __shfl_xor_sync(FULLM, sq, 1);
    float nrm = sqrtf(sq);
    return sq / (1.0f + sq) / (nrm + 1e-7f) * val;
}

// ---------------------------------------------------------------------------
// Routing mainloop (R9-proven): 10-lane groups, 3 n per group-iteration,
// 6 batched LDG.128, ILP-3 chains, f32x2 accumulators; NPW=288 n per warp.
// ---------------------------------------------------------------------------
__device__ __forceinline__ void route_pass(
    const float* vs, int b, int chunk, int warp, int lane, int g, int c,
    bool active, float* s_dst)
{
    __half2 vr2[8];
    u64t acc2[8];
#pragma unroll
    for (int q = 0; q < 8; q++) {
        vr2[q] = active ? __floats2half2_rn(vs[c * L_ + 2 * q],
                                            vs[c * L_ + 2 * q + 1])
                        : __floats2half2_rn(0.f, 0.f);
        acc2[q] = pk2(0.f, 0.f);
    }

    int base_n = chunk * 2304 + warp * 288;
    const __half* ubase = g_uh + ((size_t)b * N_ + base_n) * KDIM + c * L_;

    for (int it = 0; it < 32; it++) {
        const __half* up0 = ubase + (size_t)(it * 9 + g) * KDIM;
        const __half* up1 = up0 + (size_t)3 * KDIM;
        const __half* up2 = up0 + (size_t)6 * KDIM;
        uint4 z4 = make_uint4(0u, 0u, 0u, 0u);
        uint4 a0 = active ? *(const uint4*)up0       : z4;
        uint4 d0 = active ? *(const uint4*)(up0 + 8) : z4;
        uint4 a1 = active ? *(const uint4*)up1       : z4;
        uint4 d1 = active ? *(const uint4*)(up1 + 8) : z4;
        uint4 a2 = active ? *(const uint4*)up2       : z4;
        uint4 d2 = active ? *(const uint4*)(up2 + 8) : z4;

        const __half2* u0  = (const __half2*)&a0;
        const __half2* e0p = (const __half2*)&d0;
        const __half2* u1  = (const __half2*)&a1;
        const __half2* e1p = (const __half2*)&d1;
        const __half2* u2p = (const __half2*)&a2;
        const __half2* e2p = (const __half2*)&d2;

        __half2 p20 = __hmul2(u0[0], vr2[0]);
        __half2 p21 = __hmul2(u1[0], vr2[0]);
        __half2 p22 = __hmul2(u2p[0], vr2[0]);
#pragma unroll
        for (int q = 1; q < 4; q++) {
            p20 = __hfma2(u0[q], vr2[q], p20);
            p21 = __hfma2(u1[q], vr2[q], p21);
            p22 = __hfma2(u2p[q], vr2[q], p22);
        }
#pragma unroll
        for (int q = 0; q < 4; q++) {
            p20 = __hfma2(e0p[q], vr2[4 + q], p20);
            p21 = __hfma2(e1p[q], vr2[4 + q], p21);
            p22 = __hfma2(e2p[q], vr2[4 + q], p22);
        }
        float p0 = __low2float(p20) + __high2float(p20);
        float p1 = __low2float(p21) + __high2float(p21);
        float p2 = __low2float(p22) + __high2float(p22);

        float e0 = active ? __expf(p0) : 0.0f;
        float e1 = active ? __expf(p1) : 0.0f;
        float e2 = active ? __expf(p2) : 0.0f;

        float s0 = e0, s1 = e1, s2 = e2, t0, t1, t2;
        t0 = __shfl_sync(FULLM, s0, lane + 8);
        t1 = __shfl_sync(FULLM, s1, lane + 8);
        t2 = __shfl_sync(FULLM, s2, lane + 8);
        if (c < 2) { s0 += t0; s1 += t1; s2 += t2; }
        t0 = __shfl_sync(FULLM, s0, lane + 4);
        t1 = __shfl_sync(FULLM, s1, lane + 4);
        t2 = __shfl_sync(FULLM, s2, lane + 4);
        if (c < 4) { s0 += t0; s1 += t1; s2 += t2; }
        t0 = __shfl_sync(FULLM, s0, lane + 2);
        t1 = __shfl_sync(FULLM, s1, lane + 2);
        t2 = __shfl_sync(FULLM, s2, lane + 2);
        if (c < 2) { s0 += t0; s1 += t1; s2 += t2; }
        t0 = __shfl_sync(FULLM, s0, lane + 1);
        t1 = __shfl_sync(FULLM, s1, lane + 1);
        t2 = __shfl_sync(FULLM, s2, lane + 1);
        if (c < 1) { s0 += t0; s1 += t1; s2 += t2; }
        float se0 = __shfl_sync(FULLM, s0, g * 10);
        float se1 = __shfl_sync(FULLM, s1, g * 10);
        float se2 = __shfl_sync(FULLM, s2, g * 10);

        u64t w0 = pk2(__fdividef(e0, se0), __fdividef(e0, se0));
        u64t w1 = pk2(__fdividef(e1, se1), __fdividef(e1, se1));
        u64t w2 = pk2(__fdividef(e2, se2), __fdividef(e2, se2));
#pragma unroll
        for (int q = 0; q < 4; q++) {
            float2 f;
            f = __half22float2(u0[q]);  acc2[q]     = ffma2(pk2(f.x, f.y), w0, acc2[q]);
            f = __half22float2(e0p[q]); acc2[4 + q] = ffma2(pk2(f.x, f.y), w0, acc2[4 + q]);
            f = __half22float2(u1[q]);  acc2[q]     = ffma2(pk2(f.x, f.y), w1, acc2[q]);
            f = __half22float2(e1p[q]); acc2[4 + q] = ffma2(pk2(f.x, f.y), w1, acc2[4 + q]);
            f = __half22float2(u2p[q]); acc2[q]     = ffma2(pk2(f.x, f.y), w2, acc2[q]);
            f = __half22float2(e2p[q]); acc2[4 + q] = ffma2(pk2(f.x, f.y), w2, acc2[4 + q]);
        }
    }

    float acc[L_];
#pragma unroll
    for (int q = 0; q < 8; q++) upk2(acc2[q], acc[2 * q], acc[2 * q + 1]);
#pragma unroll
    for (int l = 0; l < L_; l++) {
        float a1 = __shfl_sync(FULLM, acc[l], lane + 10);
        float a2 = __shfl_sync(FULLM, acc[l], lane + 20);
        if (lane < 10) acc[l] += a1 + a2;
    }
    if (lane < 10) {
#pragma unroll
        for (int l = 0; l < L_; l++)
            atomicAdd(&s_dst[lane * L_ + l], acc[l]);
    }
}

// ---------------------------------------------------------------------------
// MEGA kernel: 1280 blocks x 256 threads.
//  bid <  1024 : GEMM+s0   tile 36n x 16b; bt = bid/128 (b-group 0 first)
//  bid >= 1024 : route      2 blocks per b; r1 -> sibling wait -> r2 -> out
// Spin-safety: spinning route blocks <= 256 < 3 blk/SM * 148 = 444 slots,
// GEMM never waits -> progress guaranteed under any dispatch order.
// ---------------------------------------------------------------------------
__global__ void __launch_bounds__(256) k_mega(
    const float* __restrict__ x, const float* __restrict__ W,
    const float* __restrict__ bias, float* __restrict__ out)
{
    __shared__ u64t xs[36 * 16 * IL_];   // 36 KB (GEMM x tile)
    __shared__ float vs[KDIM];           // route dot vector
    __shared__ int smflag;
    int bid = blockIdx.x;
    int t = threadIdx.x;

    if (bid < 1024) {
        // ================= GEMM + s0 =================
        int bt = bid >> 7;                // 0..7  (group of 16 b)
        int nt = bid & 127;               // 0..127
        int b0 = bt * 16;
        int n0 = nt * 36;

        for (int idx = t; idx < 36 * 16 * IL_; idx += 256) {
            int nn = idx >> 7, r = idx & 127;   // r = bi*8 + j
            int bi = r >> 3, j = r & 7;
            float val = x[(size_t)(b0 + bi) * (N_ * IL_)
                          + (size_t)(n0 + nn) * IL_ + j];
            xs[(nn * 16 + bi) * IL_ + j] = pk2(val, val);
        }
        __syncthreads();

        if (t < 240) {
            int kp = t % 80;              // k-pair
            int slot = t / 80;            // 0..2 (n slot)
            u64t s0a[16];
#pragma unroll
            for (int i = 0; i < 16; i++) s0a[i] = pk2(0.f, 0.f);

            for (int nj3 = 0; nj3 < 12; nj3++) {
                int nn = nj3 * 3 + slot;
                const float* Wn = W + (size_t)(n0 + nn) * (IL_ * KDIM) + 2 * kp;
                u64t w2[IL_];
#pragma unroll
                for (int j = 0; j < IL_; j++)
                    w2[j] = *(const u64t*)(Wn + j * KDIM);
                __half2* op = (__half2*)(g_uh
                              + ((size_t)b0 * N_ + (n0 + nn)) * KDIM + 2 * kp);
                const u64t* xp = &xs[nn * 16 * IL_];
#pragma unroll
                for (int bi = 0; bi < 16; bi++) {
                    const u64t* xb = xp + bi * IL_;
                    u64t u2 = fmul2(xb[0], w2[0]);
#pragma unroll
                    for (int j = 1; j < IL_; j++) u2 = ffma2(xb[j], w2[j], u2);
                    s0a[bi] = fadd2(s0a[bi], u2);
                    float f0, f1; upk2(u2, f0, f1);
                    op[(size_t)bi * (N_ * KDIM / 2)] = __floats2half2_rn(f0, f1);
                }
            }
#pragma unroll
            for (int bi = 0; bi < 16; bi++) {
                float f0, f1; upk2(s0a[bi], f0, f1);
                atomicAdd(&g_s[0][(b0 + bi) * KDIM + 2 * kp],     0.1f * f0);
                atomicAdd(&g_s[0][(b0 + bi) * KDIM + 2 * kp + 1], 0.1f * f1);
            }
        }
        __threadfence();
        __syncthreads();
        if (t == 0) atomicAdd(&g_cnt_gemm[bt], 1u);
        return;
    }

    // ================= ROUTE (2 blocks per b) =================
    int rid = bid - 1024;
    int b = rid >> 1;
    int chunk = rid & 1;

    // wait for this b-group's GEMM tiles (s0[b] + u[b] complete)
    if (t == 0) {
        while (*(volatile unsigned*)&g_cnt_gemm[b >> 4] < 128u)
            __nanosleep(64);
    }
    __syncthreads();
    __threadfence();

    float bval = 0.0f, v0 = 0.0f;
    if (t < KDIM) {
        bval = bias[t];
        v0 = squash16(__ldcg(&g_s[0][b * KDIM + t]) + bval);
        vs[t] = v0;
    }
    __syncthreads();

    int warp = t >> 5;
    int lane = t & 31;
    int g = (lane >= 20) ? 2 : (lane >= 10 ? 1 : 0);
    int c = lane - g * 10;
    bool active = (lane < 30);

    // round 1: logit u.v0 -> s1[b]
    route_pass(vs, b, chunk, warp, lane, g, c, active, &g_s[1][b * KDIM]);

    __threadfence();
    __syncthreads();
    if (t == 0) {
        atomicAdd(&g_cnt_r1[b], 1u);
        while (*(volatile unsigned*)&g_cnt_r1[b] < 2u) __nanosleep(32);
    }
    __syncthreads();
    __threadfence();

    if (t < KDIM)
        vs[t] = v0 + squash16(__ldcg(&g_s[1][b * KDIM + t]) + bval);
    __syncthreads();

    // round 2: logit u.(v0+v1) -> s2[b]
    route_pass(vs, b, chunk, warp, lane, g, c, active, &g_s[2][b * KDIM]);

    __threadfence();
    __syncthreads();
    if (t == 0) {
        unsigned old = atomicAdd(&g_cnt_r2[b], 1u);
        smflag = (old == 1u);    // last finisher emits the output
    }
    __syncthreads();
    if (smflag) {
        __threadfence();
        if (t < KDIM)
            out[b * KDIM + t] = squash16(__ldcg(&g_s[2][b * KDIM + t]) + bval);
    }
}

// ---------------------------------------------------------------------------
extern "C" void kernel_launch(void* const* d_in, const int* in_sizes, int n_in,
                              void* d_out, int out_size) {
    const float* x    = (const float*)d_in[0];   // [B, N, 8]
    const float* W    = (const float*)d_in[1];   // [4608, 8, 160]
    const float* bias = (const float*)d_in[2];   // [10, 16]
    float* out = (float*)d_out;                  // [128, 10, 16]
    (void)in_sizes; (void)n_in; (void)out_size;

    k_zero<<<(3 * SROW + 255) / 256, 256>>>();
    k_mega<<<1280, 256>>>(x, W, bias, out);
}

// round 17
// speedup vs baseline: 1.3472x; 1.3472x over previous
#include <cuda_runtime.h>
#include <cuda_fp16.h>
#include <cstdint>

// Problem constants
#define B_   128
#define N_   4608
#define IL_  8
#define C_   10
#define L_   16
#define KDIM 160          // C_*L_
#define SROW (B_*KDIM)    // 20480

typedef unsigned long long u64t;

// packed f32x2 helpers (sm_103a FFMA2 path — PTX only)
__device__ __forceinline__ u64t pk2(float lo, float hi) {
    u64t r; asm("mov.b64 %0,{%1,%2};" : "=l"(r) : "f"(lo), "f"(hi)); return r;
}
__device__ __forceinline__ void upk2(u64t v, float& lo, float& hi) {
    asm("mov.b64 {%0,%1},%2;" : "=f"(lo), "=f"(hi) : "l"(v));
}
__device__ __forceinline__ u64t ffma2(u64t a, u64t b, u64t c) {
    u64t d; asm("fma.rn.f32x2 %0,%1,%2,%3;" : "=l"(d) : "l"(a), "l"(b), "l"(c));
    return d;
}
__device__ __forceinline__ u64t fmul2(u64t a, u64t b) {
    u64t d; asm("mul.rn.f32x2 %0,%1,%2;" : "=l"(d) : "l"(a), "l"(b)); return d;
}
__device__ __forceinline__ u64t fadd2(u64t a, u64t b) {
    u64t d; asm("add.rn.f32x2 %0,%1,%2;" : "=l"(d) : "l"(a), "l"(b)); return d;
}

// Scratch (allocation-free rule: __device__ globals)
__device__ __half g_uh[(size_t)B_ * N_ * KDIM];   // 188 MB prediction tensor
__device__ float  g_s[3][SROW];                   // s accumulators per round
__device__ unsigned g_cnt_r1[B_];                 // per-b sibling counters
__device__ unsigned g_cnt_r2[B_];

// ---------------------------------------------------------------------------
// Zero the s accumulators + counters (must happen every replay)
// ---------------------------------------------------------------------------
__global__ void k_zero() {
    int i = blockIdx.x * blockDim.x + threadIdx.x;
    if (i < 3 * SROW) ((float*)g_s)[i] = 0.0f;
    if (i < B_) { g_cnt_r1[i] = 0u; g_cnt_r2[i] = 0u; }
}

// ---------------------------------------------------------------------------
// K1: u[b,n,k] = sum_j x[b,n,j] * W[n,j,k]  (fp32 via packed FFMA2, fp16
//     store) FUSED with s0[b,k] += 0.1 * sum_n u[b,n,k].   (R9 exact)
// ---------------------------------------------------------------------------
__global__ void __launch_bounds__(160) k_u_s0(const float* __restrict__ x,
                                              const float* __restrict__ W) {
    int b0 = blockIdx.x * 16;
    int n0 = blockIdx.y * 32;
    int t = threadIdx.x;
    int kp = t % 80;            // k-pair index
    int ns = t / 80;            // n slot (0/1)
    __shared__ u64t xs[32 * 16 * IL_];   // 32 KB, [nn][bi][j] = (x,x) pairs

    for (int idx = t; idx < 16 * 32 * IL_; idx += 160) {
        int nn = idx >> 7, r = idx & 127;     // r = bi*8 + j
        int bi = r >> 3, j = r & 7;
        float val = x[(size_t)(b0 + bi) * (N_ * IL_) + (size_t)(n0 + nn) * IL_ + j];
        xs[(nn * 16 + bi) * IL_ + j] = pk2(val, val);
    }
    __syncthreads();

    u64t s0a[16];
#pragma unroll
    for (int i = 0; i < 16; i++) s0a[i] = pk2(0.f, 0.f);

    for (int nj2 = 0; nj2 < 16; nj2++) {
        int nn = nj2 * 2 + ns;                 // this thread's n within tile
        const float* Wn = W + (size_t)(n0 + nn) * (IL_ * KDIM) + 2 * kp;
        u64t w2[IL_];
#pragma unroll
        for (int j = 0; j < IL_; j++)
            w2[j] = *(const u64t*)(Wn + j * KDIM);
        __half2* op = (__half2*)(g_uh + ((size_t)b0 * N_ + (n0 + nn)) * KDIM
                                 + 2 * kp);
        const u64t* xp = &xs[nn * 16 * IL_];
#pragma unroll
        for (int bi = 0; bi < 16; bi++) {
            const u64t* xb = xp + bi * IL_;
            u64t u2 = fmul2(xb[0], w2[0]);
#pragma unroll
            for (int j = 1; j < IL_; j++) u2 = ffma2(xb[j], w2[j], u2);
            s0a[bi] = fadd2(s0a[bi], u2);
            float f0, f1; upk2(u2, f0, f1);
            op[(size_t)bi * (N_ * KDIM / 2)] = __floats2half2_rn(f0, f1);
        }
    }
#pragma unroll
    for (int bi = 0; bi < 16; bi++) {
        float f0, f1; upk2(s0a[bi], f0, f1);
        atomicAdd(&g_s[0][(b0 + bi) * KDIM + 2 * kp],     0.1f * f0);
        atomicAdd(&g_s[0][(b0 + bi) * KDIM + 2 * kp + 1], 0.1f * f1);
    }
}

// ---------------------------------------------------------------------------
// squash on one element in an aligned 16-lane group
// ---------------------------------------------------------------------------
#define FULLM 0xffffffffu
__device__ __forceinline__ float squash16(float val) {
    float sq = val * val;
    sq += __shfl_xor_sync(FULLM, sq, 8);
    sq += __shfl_xor_sync(FULLM, sq, 4);
    sq += __shfl_xor_sync(FULLM, sq, 2);
    sq += __shfl_xor_sync(FULLM, sq, 1);
    float nrm = sqrtf(sq);
    return sq / (1.0f + sq) / (nrm + 1e-7f) * val;
}

// ---------------------------------------------------------------------------
// Routing mainloop (R9 exact): 1152 n/block, 144/warp = 16 iters x 9 n.
// 10-lane groups, 3 n per group-iteration (6 LDG.128, ILP-3), f32x2 acc.
// ---------------------------------------------------------------------------
__device__ __forceinline__ void route_pass(
    const float* vs, int b, int chunk, int warp, int lane, int g, int c,
    bool active, float* s_dst)
{
    __half2 vr2[8];
    u64t acc2[8];
#pragma unroll
    for (int q = 0; q < 8; q++) {
        vr2[q] = active ? __floats2half2_rn(vs[c * L_ + 2 * q],
                                            vs[c * L_ + 2 * q + 1])
                        : __floats2half2_rn(0.f, 0.f);
        acc2[q] = pk2(0.f, 0.f);
    }

    const int NPW = 144;
    int base_n = chunk * 1152 + warp * NPW;
    const __half* ubase = g_uh + ((size_t)b * N_ + base_n) * KDIM + c * L_;

    for (int it = 0; it < 16; it++) {
        const __half* up0 = ubase + (size_t)(it * 9 + g) * KDIM;
        const __half* up1 = up0 + (size_t)3 * KDIM;
        const __half* up2 = up0 + (size_t)6 * KDIM;
        uint4 z4 = make_uint4(0u, 0u, 0u, 0u);
        uint4 a0 = active ? *(const uint4*)up0       : z4;
        uint4 d0 = active ? *(const uint4*)(up0 + 8) : z4;
        uint4 a1 = active ? *(const uint4*)up1       : z4;
        uint4 d1 = active ? *(const uint4*)(up1 + 8) : z4;
        uint4 a2 = active ? *(const uint4*)up2       : z4;
        uint4 d2 = active ? *(const uint4*)(up2 + 8) : z4;

        const __half2* u0  = (const __half2*)&a0;
        const __half2* e0p = (const __half2*)&d0;
        const __half2* u1  = (const __half2*)&a1;
        const __half2* e1p = (const __half2*)&d1;
        const __half2* u2p = (const __half2*)&a2;
        const __half2* e2p = (const __half2*)&d2;

        __half2 p20 = __hmul2(u0[0], vr2[0]);
        __half2 p21 = __hmul2(u1[0], vr2[0]);
        __half2 p22 = __hmul2(u2p[0], vr2[0]);
#pragma unroll
        for (int q = 1; q < 4; q++) {
            p20 = __hfma2(u0[q], vr2[q], p20);
            p21 = __hfma2(u1[q], vr2[q], p21);
            p22 = __hfma2(u2p[q], vr2[q], p22);
        }
#pragma unroll
        for (int q = 0; q < 4; q++) {
            p20 = __hfma2(e0p[q], vr2[4 + q], p20);
            p21 = __hfma2(e1p[q], vr2[4 + q], p21);
            p22 = __hfma2(e2p[q], vr2[4 + q], p22);
        }
        float p0 = __low2float(p20) + __high2float(p20);
        float p1 = __low2float(p21) + __high2float(p21);
        float p2 = __low2float(p22) + __high2float(p22);

        float e0 = active ? __expf(p0) : 0.0f;
        float e1 = active ? __expf(p1) : 0.0f;
        float e2 = active ? __expf(p2) : 0.0f;

        float s0 = e0, s1 = e1, s2 = e2, t0, t1, t2;
        t0 = __shfl_sync(FULLM, s0, lane + 8);
        t1 = __shfl_sync(FULLM, s1, lane + 8);
        t2 = __shfl_sync(FULLM, s2, lane + 8);
        if (c < 2) { s0 += t0; s1 += t1; s2 += t2; }
        t0 = __shfl_sync(FULLM, s0, lane + 4);
        t1 = __shfl_sync(FULLM, s1, lane + 4);
        t2 = __shfl_sync(FULLM, s2, lane + 4);
        if (c < 4) { s0 += t0; s1 += t1; s2 += t2; }
        t0 = __shfl_sync(FULLM, s0, lane + 2);
        t1 = __shfl_sync(FULLM, s1, lane + 2);
        t2 = __shfl_sync(FULLM, s2, lane + 2);
        if (c < 2) { s0 += t0; s1 += t1; s2 += t2; }
        t0 = __shfl_sync(FULLM, s0, lane + 1);
        t1 = __shfl_sync(FULLM, s1, lane + 1);
        t2 = __shfl_sync(FULLM, s2, lane + 1);
        if (c < 1) { s0 += t0; s1 += t1; s2 += t2; }
        float se0 = __shfl_sync(FULLM, s0, g * 10);
        float se1 = __shfl_sync(FULLM, s1, g * 10);
        float se2 = __shfl_sync(FULLM, s2, g * 10);

        u64t w0 = pk2(__fdividef(e0, se0), __fdividef(e0, se0));
        u64t w1 = pk2(__fdividef(e1, se1), __fdividef(e1, se1));
        u64t w2 = pk2(__fdividef(e2, se2), __fdividef(e2, se2));
#pragma unroll
        for (int q = 0; q < 4; q++) {
            float2 f;
            f = __half22float2(u0[q]);  acc2[q]     = ffma2(pk2(f.x, f.y), w0, acc2[q]);
            f = __half22float2(e0p[q]); acc2[4 + q] = ffma2(pk2(f.x, f.y), w0, acc2[4 + q]);
            f = __half22float2(u1[q]);  acc2[q]     = ffma2(pk2(f.x, f.y), w1, acc2[q]);
            f = __half22float2(e1p[q]); acc2[4 + q] = ffma2(pk2(f.x, f.y), w1, acc2[4 + q]);
            f = __half22float2(u2p[q]); acc2[q]     = ffma2(pk2(f.x, f.y), w2, acc2[q]);
            f = __half22float2(e2p[q]); acc2[4 + q] = ffma2(pk2(f.x, f.y), w2, acc2[4 + q]);
        }
    }

    float acc[L_];
#pragma unroll
    for (int q = 0; q < 8; q++) upk2(acc2[q], acc[2 * q], acc[2 * q + 1]);
#pragma unroll
    for (int l = 0; l < L_; l++) {
        float a1 = __shfl_sync(FULLM, acc[l], lane + 10);
        float a2 = __shfl_sync(FULLM, acc[l], lane + 20);
        if (lane < 10) acc[l] += a1 + a2;
    }
    if (lane < 10) {
#pragma unroll
        for (int l = 0; l < L_; l++)
            atomicAdd(&s_dst[lane * L_ + l], acc[l]);
    }
}

// ---------------------------------------------------------------------------
// FUSED routing: round1 -> per-b sibling barrier (4 blocks) -> round2 ->
// last finisher emits out[b]. Grid (B, 4) = 512 blocks, launch_bounds(256,4)
// -> 512 <= 4x148=592 slots: all blocks co-resident, spins cannot deadlock.
// Coupling is per-b only (adjacent bids, near-simultaneous start), avoiding
// R15's global-straggler amplification.
// ---------------------------------------------------------------------------
__global__ void __launch_bounds__(256, 4) k_route_fused(
    const float* __restrict__ bias, float* __restrict__ out)
{
    int b = blockIdx.x;
    int chunk = blockIdx.y;            // 0..3
    int t = threadIdx.x;

    __shared__ float vs[KDIM];
    __shared__ int smflag;
    float bval = 0.0f, v0 = 0.0f;
    if (t < KDIM) {
        bval = bias[t];
        v0 = squash16(g_s[0][b * KDIM + t] + bval);
        vs[t] = v0;
    }
    __syncthreads();

    int warp = t >> 5;
    int lane = t & 31;
    int g = (lane >= 20) ? 2 : (lane >= 10 ? 1 : 0);
    int c = lane - g * 10;
    bool active = (lane < 30);

    // ---- round 1: logit u.v0 -> s1[b]
    route_pass(vs, b, chunk, warp, lane, g, c, active, &g_s[1][b * KDIM]);

    // ---- per-b sibling barrier (4 blocks)
    __threadfence();
    __syncthreads();
    if (t == 0) {
        atomicAdd(&g_cnt_r1[b], 1u);
        while (*(volatile unsigned*)&g_cnt_r1[b] < 4u) __nanosleep(32);
    }
    __syncthreads();
    __threadfence();

    // ---- round 2 prologue: vs = v0 + v1
    if (t < KDIM)
        vs[t] = v0 + squash16(__ldcg(&g_s[1][b * KDIM + t]) + bval);
    __syncthreads();

    // ---- round 2: logit u.(v0+v1) -> s2[b]
    route_pass(vs, b, chunk, warp, lane, g, c, active, &g_s[2][b * KDIM]);

    // ---- last of the 4 siblings emits the output
    __threadfence();
    __syncthreads();
    if (t == 0) {
        unsigned old = atomicAdd(&g_cnt_r2[b], 1u);
        smflag = (old == 3u);
    }
    __syncthreads();
    if (smflag) {
        __threadfence();
        if (t < KDIM)
            out[b * KDIM + t] = squash16(__ldcg(&g_s[2][b * KDIM + t]) + bval);
    }
}

// ---------------------------------------------------------------------------
extern "C" void kernel_launch(void* const* d_in, const int* in_sizes, int n_in,
                              void* d_out, int out_size) {
    const float* x    = (const float*)d_in[0];   // [B, N, 8]
    const float* W    = (const float*)d_in[1];   // [4608, 8, 160]
    const float* bias = (const float*)d_in[2];   // [10, 16]
    float* out = (float*)d_out;                  // [128, 10, 16]
    (void)in_sizes; (void)n_in; (void)out_size;

    k_zero<<<(3 * SROW + 255) / 256, 256>>>();
    k_u_s0<<<dim3(B_ / 16, N_ / 32), 160>>>(x, W);
    k_route_fused<<<dim3(B_, 4), 256>>>(bias, out);
}